// round 9
// baseline (speedup 1.0000x reference)
#include <cuda_runtime.h>
#include <cuda_bf16.h>

// Problem constants (fixed by setup_inputs):
//   encoder_output: (B=32, L_ENC=512, E=256) float32
//   durations:      (B=32, L_ENC=512) int32, values in [0, 8)
//   output:         (B=32, L_DEC=2048, E=256) float32
//
// out[b, d, :] = enc[b, l, :] where cs[l-1] <= d < cs[l]; 0 for d >= cs[511].

#define B_SZ    32
#define L_ENC   512
#define L_DEC   2048
#define E_DIM   256
#define E_VEC   (E_DIM / 4)        // 64 float4 per row
#define ROWS_PER_BLOCK 8           // encoder rows per scatter block
#define SCATTER_BLOCKS (L_ENC / ROWS_PER_BLOCK)   // 64
#define PAD_BLOCKS 4
#define PAD_STRIPE (L_DEC / PAD_BLOCKS)           // 512

// Per-batch inclusive cumsum of durations.
__device__ int g_cs[B_SZ * L_ENC];

// ---------------------------------------------------------------------------
// Kernel A: per-batch inclusive scan of durations. One block per batch.
// ---------------------------------------------------------------------------
__global__ void lr_cumsum_kernel(const int* __restrict__ dur)
{
    __shared__ int warp_sums[16];
    const int b    = blockIdx.x;
    const int t    = threadIdx.x;
    const int wid  = t >> 5;
    const int lane = t & 31;

    int v = dur[b * L_ENC + t];

    #pragma unroll
    for (int off = 1; off < 32; off <<= 1) {
        int u = __shfl_up_sync(0xffffffffu, v, off);
        if (lane >= off) v += u;
    }
    if (lane == 31) warp_sums[wid] = v;
    __syncthreads();

    if (wid == 0 && lane < 16) {
        int ws = warp_sums[lane];
        #pragma unroll
        for (int off = 1; off < 16; off <<= 1) {
            int u = __shfl_up_sync(0x0000ffffu, ws, off);
            if (lane >= off) ws += u;
        }
        warp_sums[lane] = ws - warp_sums[lane];   // exclusive prefix of sums
    }
    __syncthreads();

    g_cs[b * L_ENC + t] = v + warp_sums[wid];
}

// ---------------------------------------------------------------------------
// Kernel B: SCATTER. Grid (SCATTER_BLOCKS + PAD_BLOCKS, B), 512 threads.
//
// Scatter blocks (x < 64): 8 groups of 64 lanes; group g owns encoder row
// l = x*8+g. It loads the 1 KB enc row once (address independent of any
// prior load -> issues immediately), reads its span [cs[l-1], cs[l]) from
// smem-staged cumsum, and streams `dur` coalesced 1 KB row-stores.
//
// Pad blocks (x >= 64): zero-fill decoder rows [total, L_DEC) within the
// block's stripe of 512 decoder rows.
// ---------------------------------------------------------------------------
__global__ void __launch_bounds__(512)
lr_scatter_kernel(const float4* __restrict__ enc, float4* __restrict__ out)
{
    const int b = blockIdx.y;
    const int x = blockIdx.x;
    const int t = threadIdx.x;
    const int group = t >> 6;        // 0..7
    const int lane  = t & 63;        // 0..63

    float4* out_b = out + (long)b * L_DEC * E_VEC;

    if (x < SCATTER_BLOCKS) {
        // ---- scatter path ----
        __shared__ int s_cs[ROWS_PER_BLOCK + 1];   // cs[l0-1 .. l0+7]
        const int l0 = x * ROWS_PER_BLOCK;

        if (t <= ROWS_PER_BLOCK) {
            const int idx = l0 - 1 + t;
            s_cs[t] = (idx >= 0) ? g_cs[b * L_ENC + idx] : 0;
        }

        // Enc row load: independent of cumsum, issues in parallel.
        const int l = l0 + group;
        const float4 v = __ldg(enc + ((long)(b * L_ENC + l)) * E_VEC + lane);

        __syncthreads();

        const int excl = s_cs[group];
        int incl = s_cs[group + 1];
        if (incl > L_DEC) incl = L_DEC;

        // Stream dur consecutive coalesced row-stores (independent ops).
        for (int d = excl; d < incl; ++d)
            out_b[(long)d * E_VEC + lane] = v;
    } else {
        // ---- padding path ----
        const int p = x - SCATTER_BLOCKS;
        const int sstart = p * PAD_STRIPE;
        const int send   = sstart + PAD_STRIPE;

        const int total = g_cs[b * L_ENC + (L_ENC - 1)];
        int d0 = total > sstart ? total : sstart;

        const float4 z = make_float4(0.f, 0.f, 0.f, 0.f);
        // 8 groups stride the pad rows.
        for (int d = d0 + group; d < send; d += 8) {
            // align group phase: ensure each row handled by exactly one group
            // (d0+group..send step 8 covers each row once since groups 0..7)
            out_b[(long)d * E_VEC + lane] = z;
        }
    }
}

// ---------------------------------------------------------------------------
extern "C" void kernel_launch(void* const* d_in, const int* in_sizes, int n_in,
                              void* d_out, int out_size)
{
    const float* enc = (const float*)d_in[0];     // (B, L_ENC, E)
    const int*   dur = (const int*)d_in[1];       // (B, L_ENC) int32
    (void)in_sizes; (void)n_in; (void)out_size;

    lr_cumsum_kernel<<<B_SZ, L_ENC>>>(dur);

    dim3 grid(SCATTER_BLOCKS + PAD_BLOCKS, B_SZ);
    lr_scatter_kernel<<<grid, 512>>>((const float4*)enc, (float4*)d_out);
}